// round 7
// baseline (speedup 1.0000x reference)
#include <cuda_runtime.h>
#include <math.h>
#include <stdint.h>
#include <stddef.h>

#define B 32
#define TIN 512
#define E 576
#define TOUT 400
#define NMEL 80
#define PRE 256
#define ARNN 1024
#define DRNN 1024
#define ADIM 128
#define NF 32
#define KS 31

#define KA (PRE + E + ARNN)    /* 1856 : [xt | ctx | ah] */
#define NA (3 * ARNN)          /* 3072 : gates i,f,g (o-gate dead: ah=ac) */
#define KD (ARNN + E + DRNN)   /* 2624 : [ah | ctx | dh] */
#define ND (4 * DRNN)          /* 4096 */

#define NBLK 148
#define SKA 6                  /* split-K for att GEMM: 24 ntiles x 6 = 144 blocks */
#define SKD 4                  /* split-K for dec GEMM: 32 ntiles x 4 = 128 blocks */
#define KPB_A 320              /* 1856 -> 320*5 + 256, all multiples of 16 */
#define KPB_D 656              /* 2624 / 4, multiple of 16 */

#define GATE_OFF  ((size_t)B * NMEL * TOUT)
#define ALIGN_OFF (GATE_OFF + (size_t)B * TOUT)

// --------------------------- device scratch ---------------------------
__device__ float g_di[(size_t)TOUT * B * NMEL];
__device__ float g_h1[(size_t)TOUT * B * PRE];
__device__ float g_xs[(size_t)TOUT * B * PRE];
__device__ float g_pmem[(size_t)B * TIN * ADIM];
__device__ float g_Wa[(size_t)NA * KA];
__device__ float g_Wd[(size_t)ND * KD];
__device__ float g_ba[NA];
__device__ float g_bd[ND];
__device__ float g_qWt[(size_t)ARNN * ADIM];        // [k][d]
__device__ float g_pgW[(size_t)(DRNN + E) * 81];    // [j][k], k=80 -> gate row
__device__ float g_cinA[B * KA];
__device__ float g_cinD[B * KD];
__device__ float g_ac[B * ARNN];
__device__ float g_dc[B * DRNN];
__device__ float g_aw[B * TIN];
__device__ float g_awc[B * TIN];
__device__ float g_qp[B * 4 * ADIM];
__device__ float g_en[B * TIN];
__device__ float g_gAp[(size_t)SKA * B * NA];
__device__ float g_gDp[(size_t)SKD * B * ND];

__device__ unsigned g_cnt = 0;
__device__ volatile unsigned g_gen = 0;

__device__ __forceinline__ float sigf(float x) { return 1.f / (1.f + expf(-x)); }

// --------------------------- grid barrier ------------------------------
__device__ __forceinline__ void gsync() {
    __threadfence();              // publish this thread's writes (+ IVALL)
    __syncthreads();
    if (threadIdx.x == 0) {
        unsigned gen = g_gen;     // snapshot BEFORE arriving
        unsigned t = atomicAdd(&g_cnt, 1);
        if (t == NBLK - 1) {
            *(volatile unsigned*)&g_cnt = 0;
            __threadfence();
            g_gen = gen + 1;
        } else {
            while (g_gen == gen) {}
        }
        __threadfence();          // acquire: invalidate L1 before reads
    }
    __syncthreads();
}

// --------------------------- precompute kernels ------------------------
__global__ void build_di(const float* __restrict__ dec) {
    int i = blockIdx.x * 256 + threadIdx.x;
    if (i >= TOUT * B * NMEL) return;
    int k = i % NMEL;
    int r = i / NMEL;
    int b = r % B;
    int t = r / B;
    g_di[i] = (t == 0) ? 0.f : dec[((size_t)b * TOUT + (t - 1)) * NMEL + k];
}

__global__ void pack_weights(const float* __restrict__ aWih, const float* __restrict__ aWhh,
                             const float* __restrict__ abih, const float* __restrict__ abhh,
                             const float* __restrict__ dWih, const float* __restrict__ dWhh,
                             const float* __restrict__ dbih, const float* __restrict__ dbhh,
                             const float* __restrict__ qW,   const float* __restrict__ projW,
                             const float* __restrict__ gateW) {
    size_t stride = (size_t)gridDim.x * blockDim.x;
    for (size_t i = (size_t)blockIdx.x * blockDim.x + threadIdx.x;
         i < (size_t)ND * KD; i += stride) {
        {
            size_t r = i / KD, k = i % KD;
            g_Wd[i] = (k < (ARNN + E)) ? dWih[r * (ARNN + E) + k]
                                       : dWhh[r * DRNN + (k - (ARNN + E))];
        }
        if (i < (size_t)NA * KA) {
            size_t r = i / KA, k = i % KA;
            g_Wa[i] = (k < (PRE + E)) ? aWih[r * (PRE + E) + k]
                                      : aWhh[r * ARNN + (k - (PRE + E))];
        }
        if (i < NA) g_ba[i] = abih[i] + abhh[i];
        if (i < ND) g_bd[i] = dbih[i] + dbhh[i];
        if (i < (size_t)ARNN * ADIM) {
            size_t k = i / ADIM, d = i % ADIM;
            g_qWt[i] = qW[d * ARNN + k];
        }
        if (i < (size_t)(DRNN + E) * 81) {
            size_t j = i / 81, k = i % 81;
            g_pgW[i] = (k < 80) ? projW[k * (DRNN + E) + j] : gateW[j];
        }
    }
}

__global__ void zero_state() {
    int i = blockIdx.x * blockDim.x + threadIdx.x;
    if (i < B * ARNN) g_ac[i] = 0.f;
    if (i < B * DRNN) g_dc[i] = 0.f;
    if (i < B * TIN) { g_aw[i] = 0.f; g_awc[i] = 0.f; }
    if (i < B * KD) g_cinD[i] = 0.f;
    if (i < B * KA) {
        int b = i / KA, j = i % KA;
        g_cinA[i] = (j < PRE) ? g_xs[(size_t)b * PRE + j] : 0.f;
    }
}

// ---------- precompute GEMM (prenet / pmem): C = act(A@W^T) ------------
__global__ __launch_bounds__(256) void gemm32(const float* __restrict__ A,
                                              const float* __restrict__ W,
                                              float* __restrict__ C,
                                              int N, int K, int relu) {
    __shared__ float As[32][33];
    __shared__ float Ws[32][33];
    int tid = threadIdx.x;
    int n0 = blockIdx.x * 32, m0 = blockIdx.y * 32;
    int tm = (tid >> 4) << 1, tn = (tid & 15) << 1;
    float a00 = 0.f, a01 = 0.f, a10 = 0.f, a11 = 0.f;
    for (int kt = 0; kt < K; kt += 32) {
#pragma unroll
        for (int i = 0; i < 4; i++) {
            int id = tid + i * 256;
            int r = id >> 5, kk = id & 31;
            int k = kt + kk;
            As[r][kk] = (k < K) ? A[(size_t)(m0 + r) * K + k] : 0.f;
            Ws[r][kk] = (k < K) ? W[(size_t)(n0 + r) * K + k] : 0.f;
        }
        __syncthreads();
#pragma unroll
        for (int kk = 0; kk < 32; kk++) {
            float x0 = As[tm][kk], x1 = As[tm + 1][kk];
            float y0 = Ws[tn][kk], y1 = Ws[tn + 1][kk];
            a00 += x0 * y0; a01 += x0 * y1;
            a10 += x1 * y0; a11 += x1 * y1;
        }
        __syncthreads();
    }
    if (relu) {
        a00 = fmaxf(a00, 0.f); a01 = fmaxf(a01, 0.f);
        a10 = fmaxf(a10, 0.f); a11 = fmaxf(a11, 0.f);
    }
    size_t o = (size_t)(m0 + tm) * N + n0 + tn;
    C[o] = a00; C[o + 1] = a01;
    C[o + N] = a10; C[o + N + 1] = a11;
}

// ---------------- persistent-kernel GEMM phase -------------------------
// Partial C[32][128] at (n0, k-range [k0,k0+kl)), 4x4 per thread, f4 tiles.
__device__ __forceinline__ void gemm_phase(const float* __restrict__ A,
                                           const float* __restrict__ W,
                                           float* __restrict__ Cp, int Ntot,
                                           int n0, int k0, int kl, int Krow,
                                           float* sm) {
    float* sA = sm;          // [16][36]
    float* sW = sm + 576;    // [16][132]
    int tid = threadIdx.x;
    int tx = tid & 31;       // n quad
    int ty = tid >> 5;       // m quad (== warp id -> a-loads broadcast)
    float acc[4][4];
#pragma unroll
    for (int i = 0; i < 4; i++)
#pragma unroll
        for (int j = 0; j < 4; j++) acc[i][j] = 0.f;

    for (int kt = k0; kt < k0 + kl; kt += 16) {
        if (tid < 128) {
            int row = tid >> 2, kc = tid & 3;
            float4 v = *(const float4*)(A + (size_t)row * Krow + kt + kc * 4);
            sA[(kc * 4 + 0) * 36 + row] = v.x;
            sA[(kc * 4 + 1) * 36 + row] = v.y;
            sA[(kc * 4 + 2) * 36 + row] = v.z;
            sA[(kc * 4 + 3) * 36 + row] = v.w;
        }
#pragma unroll
        for (int i = 0; i < 2; i++) {
            int id = tid + i * 256;
            int row = id >> 2, kc = id & 3;
            float4 v = *(const float4*)(W + (size_t)(n0 + row) * Krow + kt + kc * 4);
            sW[(kc * 4 + 0) * 132 + row] = v.x;
            sW[(kc * 4 + 1) * 132 + row] = v.y;
            sW[(kc * 4 + 2) * 132 + row] = v.z;
            sW[(kc * 4 + 3) * 132 + row] = v.w;
        }
        __syncthreads();
#pragma unroll
        for (int kk = 0; kk < 16; kk++) {
            float4 a = *(const float4*)(sA + kk * 36 + (ty << 2));
            float4 w = *(const float4*)(sW + kk * 132 + (tx << 2));
            acc[0][0] += a.x * w.x; acc[0][1] += a.x * w.y;
            acc[0][2] += a.x * w.z; acc[0][3] += a.x * w.w;
            acc[1][0] += a.y * w.x; acc[1][1] += a.y * w.y;
            acc[1][2] += a.y * w.z; acc[1][3] += a.y * w.w;
            acc[2][0] += a.z * w.x; acc[2][1] += a.z * w.y;
            acc[2][2] += a.z * w.z; acc[2][3] += a.z * w.w;
            acc[3][0] += a.w * w.x; acc[3][1] += a.w * w.y;
            acc[3][2] += a.w * w.z; acc[3][3] += a.w * w.w;
        }
        __syncthreads();
    }
#pragma unroll
    for (int i = 0; i < 4; i++) {
        int m = (ty << 2) + i;
        float4 v = make_float4(acc[i][0], acc[i][1], acc[i][2], acc[i][3]);
        *(float4*)(Cp + (size_t)m * Ntot + n0 + (tx << 2)) = v;
    }
}

// --------------------------- persistent kernel -------------------------
__global__ __launch_bounds__(256) void decoder_loop(const float* __restrict__ memory,
                                                    const int* __restrict__ mlen,
                                                    const float* __restrict__ convW,
                                                    const float* __restrict__ convb,
                                                    const float* __restrict__ locW,
                                                    const float* __restrict__ vW,
                                                    const float* __restrict__ projb,
                                                    const float* __restrict__ gateb,
                                                    float* __restrict__ out) {
    __shared__ __align__(16) float smem[10752];
    int bid = blockIdx.x, tid = threadIdx.x;

    for (int t = 0; t < TOUT; t++) {
        // ---------------- P1: attention GEMM (144 blocks) ----------------
        if (bid < 24 * SKA) {
            int nt = bid % 24, ks = bid / 24;
            int k0 = ks * KPB_A;
            int kl = (KA - k0 < KPB_A) ? (KA - k0) : KPB_A;
            gemm_phase(g_cinA, g_Wa, g_gAp + (size_t)ks * B * NA, NA,
                       nt * 128, k0, kl, KA, smem);
        }
        gsync();

        // -------- P2: att cell update + q partial (128 blocks) ------------
        if (bid < 128) {
            float* sAh  = smem;
            float* sRed = smem + 256;
            int b = bid >> 2, qt = bid & 3;
            int j = qt * 256 + tid;
            float gi = g_ba[j], gf = g_ba[ARNN + j], gg = g_ba[2 * ARNN + j];
#pragma unroll
            for (int s = 0; s < SKA; s++) {
                const float* gp = g_gAp + ((size_t)s * B + b) * NA;
                gi += gp[j]; gf += gp[ARNN + j]; gg += gp[2 * ARNN + j];
            }
            float c = sigf(gf) * g_ac[b * ARNN + j] + sigf(gi) * tanhf(gg);
            g_ac[b * ARNN + j] = c;
            g_cinA[b * KA + (PRE + E) + j] = c;   // next-step Whh input
            g_cinD[b * KD + j] = c;               // this-step decoder input
            sAh[tid] = c;
            __syncthreads();
            int d = tid & (ADIM - 1), half = tid >> 7;
            const float* qw = g_qWt + ((size_t)(qt * 256 + half * 128)) * ADIM + d;
            float acc = 0.f;
#pragma unroll 8
            for (int k = 0; k < 128; k++)
                acc += sAh[half * 128 + k] * qw[(size_t)k * ADIM];
            sRed[tid] = acc;
            __syncthreads();
            if (tid < ADIM)
                g_qp[(b * 4 + qt) * ADIM + tid] = sRed[tid] + sRed[128 + tid];
        }
        gsync();

        // -------- P3: location conv + energies (128 blocks) ---------------
        if (bid < 128) {
            int b = bid >> 2, tq = bid & 3;
            int t0 = tq * 128;
            int len = mlen[b];
            if (t0 < len) {
                float* sQ   = smem;          // 128
                float* sV   = smem + 128;    // 128
                float* sAw  = smem + 256;    // 158
                float* sAwc = smem + 414;    // 158
                float* sCW  = smem + 572;    // 1984
                float* sLW  = smem + 2556;   // 4096 [f][d]
                float* sLR  = smem + 6652;   // 4096 [tl][f]
                if (tid < 128) {
                    float q = 0.f;
#pragma unroll
                    for (int p = 0; p < 4; p++) q += g_qp[(b * 4 + p) * ADIM + tid];
                    sQ[tid] = q;
                    sV[tid] = vW[tid];
                }
                for (int i = tid; i < NF * 2 * KS; i += 256) sCW[i] = convW[i];
                for (int i = tid; i < NF * ADIM; i += 256) {
                    int f = i & 31, d = i >> 5;
                    sLW[f * ADIM + d] = locW[d * NF + f];
                }
                for (int i = tid; i < 158; i += 256) {
                    int tt = t0 - (KS / 2) + i;
                    bool ok = (tt >= 0 && tt < TIN);
                    sAw[i]  = ok ? g_aw[b * TIN + tt]  : 0.f;
                    sAwc[i] = ok ? g_awc[b * TIN + tt] : 0.f;
                }
                __syncthreads();
                int tmax = len - t0; if (tmax > 128) tmax = 128;
                for (int i = tid; i < tmax * NF; i += 256) {
                    int tl = i >> 5, f = i & 31;
                    float acc = convb[f];
                    const float* w0 = sCW + f * 2 * KS;
                    const float* w1 = w0 + KS;
#pragma unroll
                    for (int k = 0; k < KS; k++)
                        acc += w0[k] * sAw[tl + k] + w1[k] * sAwc[tl + k];
                    sLR[tl * NF + f] = acc;
                }
                __syncthreads();
                int w = tid >> 5, lane = tid & 31;
                for (int tl = w; tl < tmax; tl += 8) {
                    float x0 = sQ[lane]       + g_pmem[((size_t)b * TIN + t0 + tl) * ADIM + lane];
                    float x1 = sQ[lane + 32]  + g_pmem[((size_t)b * TIN + t0 + tl) * ADIM + lane + 32];
                    float x2 = sQ[lane + 64]  + g_pmem[((size_t)b * TIN + t0 + tl) * ADIM + lane + 64];
                    float x3 = sQ[lane + 96]  + g_pmem[((size_t)b * TIN + t0 + tl) * ADIM + lane + 96];
                    const float* lr = sLR + tl * NF;
#pragma unroll
                    for (int f = 0; f < NF; f++) {
                        float r = lr[f];
                        x0 += r * sLW[f * ADIM + lane];
                        x1 += r * sLW[f * ADIM + lane + 32];
                        x2 += r * sLW[f * ADIM + lane + 64];
                        x3 += r * sLW[f * ADIM + lane + 96];
                    }
                    float e = tanhf(x0) * sV[lane] + tanhf(x1) * sV[lane + 32]
                            + tanhf(x2) * sV[lane + 64] + tanhf(x3) * sV[lane + 96];
#pragma unroll
                    for (int o = 16; o > 0; o >>= 1)
                        e += __shfl_down_sync(0xffffffffu, e, o);
                    if (lane == 0) g_en[b * TIN + t0 + tl] = e;
                }
            }
        }
        gsync();

        // -------- P4: softmax + context + align out (128 blocks) ----------
        if (bid < 128) {
            float* sAw  = smem;          // 512
            float* sRed = smem + 512;    // 256
            int b = bid >> 2, ec = bid & 3;
            int e0 = ec * 144;
            int len = mlen[b];
            float v1 = (tid < len) ? g_en[b * TIN + tid] : -1e30f;
            float v2 = (tid + 256 < len) ? g_en[b * TIN + tid + 256] : -1e30f;
            sRed[tid] = fmaxf(v1, v2);
            __syncthreads();
            for (int s = 128; s > 0; s >>= 1) {
                if (tid < s) sRed[tid] = fmaxf(sRed[tid], sRed[tid + s]);
                __syncthreads();
            }
            float mx = sRed[0];
            __syncthreads();
            float x1 = (tid < len) ? expf(v1 - mx) : 0.f;
            float x2 = (tid + 256 < len) ? expf(v2 - mx) : 0.f;
            sRed[tid] = x1 + x2;
            __syncthreads();
            for (int s = 128; s > 0; s >>= 1) {
                if (tid < s) sRed[tid] += sRed[tid + s];
                __syncthreads();
            }
            float inv = 1.f / sRed[0];
            float aw1 = x1 * inv, aw2 = x2 * inv;
            sAw[tid] = aw1;
            sAw[tid + 256] = aw2;
            if (ec == 0) {
                g_aw[b * TIN + tid] = aw1;
                g_aw[b * TIN + tid + 256] = aw2;
                g_awc[b * TIN + tid] += aw1;
                g_awc[b * TIN + tid + 256] += aw2;
                out[ALIGN_OFF + ((size_t)b * TOUT + t) * TIN + tid] = aw1;
                out[ALIGN_OFF + ((size_t)b * TOUT + t) * TIN + tid + 256] = aw2;
            }
            __syncthreads();
            if (tid < 144) {
                int e = e0 + tid;
                float acc = 0.f;
                const float* mp = memory + (size_t)b * TIN * E + e;
                for (int tt = 0; tt < len; tt++)
                    acc += sAw[tt] * mp[(size_t)tt * E];
                g_cinA[b * KA + PRE + e] = acc;    // next-step att ctx
                g_cinD[b * KD + ARNN + e] = acc;   // this-step dec ctx
            }
        }
        gsync();

        // ---------------- P5: decoder GEMM (128 blocks) -------------------
        if (bid < 32 * SKD) {
            int nt = bid % 32, ks = bid / 32;
            gemm_phase(g_cinD, g_Wd, g_gDp + (size_t)ks * B * ND, ND,
                       nt * 128, ks * KPB_D, KPB_D, KD, smem);
        }
        gsync();

        // ------ P6: dec cell update + mel/gate proj + next xt (32 blocks) --
        if (bid < 32) {
            float* sIn   = smem;          // 1600
            float* sPart = smem + 1600;   // 243
            int b = bid;
#pragma unroll
            for (int r = 0; r < 4; r++) {
                int j = tid + r * 256;
                float gi = g_bd[j], gf = g_bd[DRNN + j],
                      gg = g_bd[2 * DRNN + j], go = g_bd[3 * DRNN + j];
#pragma unroll
                for (int s = 0; s < SKD; s++) {
                    const float* gp = g_gDp + ((size_t)s * B + b) * ND;
                    gi += gp[j]; gf += gp[DRNN + j];
                    gg += gp[2 * DRNN + j]; go += gp[3 * DRNN + j];
                }
                float c = sigf(gf) * g_dc[b * DRNN + j] + sigf(gi) * tanhf(gg);
                g_dc[b * DRNN + j] = c;
                float h = sigf(go) * tanhf(c);
                sIn[j] = h;
                g_cinD[b * KD + (ARNN + E) + j] = h;   // next-step Whh input
            }
#pragma unroll
            for (int r = 0; r < 3; r++) {
                int j = tid + r * 256;
                if (j < E) sIn[DRNN + j] = g_cinD[b * KD + ARNN + j];
            }
            __syncthreads();
            if (tid < 243) {
                int part = tid / 81, o = tid - part * 81;
                int j0 = part * 534;
                int j1 = (part == 2) ? 1600 : j0 + 534;
                float acc = 0.f;
                for (int j = j0; j < j1; j++)
                    acc += sIn[j] * g_pgW[(size_t)j * 81 + o];
                sPart[tid] = acc;
            }
            __syncthreads();
            if (tid < 81) {
                float tot = sPart[tid] + sPart[81 + tid] + sPart[162 + tid];
                if (tid < 80) out[((size_t)b * NMEL + tid) * TOUT + t] = tot + projb[tid];
                else          out[GATE_OFF + (size_t)b * TOUT + t] = tot + gateb[0];
            }
            if (t + 1 < TOUT)
                g_cinA[b * KA + tid] = g_xs[((size_t)(t + 1) * B + b) * PRE + tid];
        }
        gsync();
    }
}

// ------------------------------ host ----------------------------------
extern "C" void kernel_launch(void* const* d_in, const int* in_sizes, int n_in,
                              void* d_out, int out_size) {
    const float* memory = (const float*)d_in[0];
    const float* dec    = (const float*)d_in[1];
    const float* pW1    = (const float*)d_in[2];
    const float* pW2    = (const float*)d_in[3];
    const float* aWih   = (const float*)d_in[4];
    const float* aWhh   = (const float*)d_in[5];
    const float* abih   = (const float*)d_in[6];
    const float* abhh   = (const float*)d_in[7];
    const float* qW     = (const float*)d_in[8];
    const float* memW   = (const float*)d_in[9];
    const float* convW  = (const float*)d_in[10];
    const float* convb  = (const float*)d_in[11];
    const float* locW   = (const float*)d_in[12];
    const float* vW     = (const float*)d_in[13];
    const float* dWih   = (const float*)d_in[14];
    const float* dWhh   = (const float*)d_in[15];
    const float* dbih   = (const float*)d_in[16];
    const float* dbhh   = (const float*)d_in[17];
    const float* projW  = (const float*)d_in[18];
    const float* projb  = (const float*)d_in[19];
    const float* gateW  = (const float*)d_in[20];
    const float* gateb  = (const float*)d_in[21];
    const int*   mlen   = (const int*)d_in[22];
    float* out = (float*)d_out;

    void* p;
    float *di, *h1, *xs;
    cudaGetSymbolAddress(&p, g_di); di = (float*)p;
    cudaGetSymbolAddress(&p, g_h1); h1 = (float*)p;
    cudaGetSymbolAddress(&p, g_xs); xs = (float*)p;
    float* pmem; cudaGetSymbolAddress(&p, g_pmem); pmem = (float*)p;

    // ---- precompute (6 nodes) ----
    build_di<<<(TOUT * B * NMEL + 255) / 256, 256>>>(dec);
    gemm32<<<dim3(PRE / 32, TOUT * B / 32), 256>>>(di, pW1, h1, PRE, NMEL, 1);
    gemm32<<<dim3(PRE / 32, TOUT * B / 32), 256>>>(h1, pW2, xs, PRE, PRE, 1);
    gemm32<<<dim3(ADIM / 32, B * TIN / 32), 256>>>(memory, memW, pmem, ADIM, E, 0);
    pack_weights<<<2048, 256>>>(aWih, aWhh, abih, abhh, dWih, dWhh, dbih, dbhh,
                                qW, projW, gateW);
    zero_state<<<(B * KD + 255) / 256, 256>>>();

    // ---- whole 400-step recurrence: one persistent kernel (1 node) ----
    decoder_loop<<<NBLK, 256>>>(memory, mlen, convW, convb, locW, vW,
                                projb, gateb, out);
}

// round 8
// speedup vs baseline: 1.0455x; 1.0455x over previous
#include <cuda_runtime.h>
#include <math.h>
#include <stdint.h>
#include <stddef.h>

#define B 32
#define TIN 512
#define E 576
#define TOUT 400
#define NMEL 80
#define PRE 256
#define ARNN 1024
#define DRNN 1024
#define ADIM 128
#define NF 32
#define KS 31

#define KA (PRE + E + ARNN)    /* 1856 : [xt | ctx | ah] */
#define NA (3 * ARNN)          /* 3072 : gates i,f,g (o-gate dead: ah=ac) */
#define KD (ARNN + E + DRNN)   /* 2624 : [ah | ctx | dh] */
#define ND (4 * DRNN)          /* 4096 */

#define NBLK 148
#define SKA 6                  /* att split-K: 24 ntiles x 6 = 144 blocks */
#define SKD 4                  /* dec split-K: 32 ntiles x 4 = 128 blocks */
#define KPB_A 312              /* 1856 = 312*5 + 296, multiples of 8 */
#define KPB_D 656              /* 2624 / 4 */

#define GATE_OFF  ((size_t)B * NMEL * TOUT)
#define ALIGN_OFF (GATE_OFF + (size_t)B * TOUT)

// --------------------------- device scratch ---------------------------
__device__ float g_di[(size_t)TOUT * B * NMEL];
__device__ float g_h1[(size_t)TOUT * B * PRE];
__device__ float g_xs[(size_t)TOUT * B * PRE];
__device__ float g_pmem[(size_t)B * TIN * ADIM];
__device__ float g_Wa[(size_t)NA * KA];
__device__ float g_Wd[(size_t)ND * KD];
__device__ float g_ba[NA];
__device__ float g_bd[ND];
__device__ float g_qWt[(size_t)ARNN * ADIM];        // [k][d]
__device__ float g_pgW[(size_t)(DRNN + E) * 81];    // [j][k], k=80 -> gate row
__device__ float g_cinA[B * KA];
__device__ float g_cinD[B * KD];
__device__ float g_ac[B * ARNN];
__device__ float g_dc[B * DRNN];
__device__ float g_aw[B * TIN];
__device__ float g_awc[B * TIN];
__device__ float g_qp[B * 4 * ADIM];
__device__ float g_en[B * TIN];
__device__ float g_gAp[(size_t)SKA * B * NA];
__device__ float g_gDp[(size_t)SKD * B * ND];

__device__ unsigned g_cnt = 0;
__device__ volatile unsigned g_gen = 0;

__device__ __forceinline__ float sigf(float x) { return 1.f / (1.f + expf(-x)); }

// --------------------------- grid barrier ------------------------------
__device__ __forceinline__ void gsync() {
    __threadfence();
    __syncthreads();
    if (threadIdx.x == 0) {
        unsigned gen = g_gen;
        unsigned t = atomicAdd(&g_cnt, 1);
        if (t == NBLK - 1) {
            *(volatile unsigned*)&g_cnt = 0;
            __threadfence();
            g_gen = gen + 1;
        } else {
            while (g_gen == gen) {}
        }
        __threadfence();
    }
    __syncthreads();
}

// --------------------------- precompute kernels ------------------------
__global__ void build_di(const float* __restrict__ dec) {
    int i = blockIdx.x * 256 + threadIdx.x;
    if (i >= TOUT * B * NMEL) return;
    int k = i % NMEL;
    int r = i / NMEL;
    int b = r % B;
    int t = r / B;
    g_di[i] = (t == 0) ? 0.f : dec[((size_t)b * TOUT + (t - 1)) * NMEL + k];
}

// pack weights + zero recurrent state (xs must already be computed)
__global__ void pack_weights(const float* __restrict__ aWih, const float* __restrict__ aWhh,
                             const float* __restrict__ abih, const float* __restrict__ abhh,
                             const float* __restrict__ dWih, const float* __restrict__ dWhh,
                             const float* __restrict__ dbih, const float* __restrict__ dbhh,
                             const float* __restrict__ qW,   const float* __restrict__ projW,
                             const float* __restrict__ gateW) {
    size_t stride = (size_t)gridDim.x * blockDim.x;
    for (size_t i = (size_t)blockIdx.x * blockDim.x + threadIdx.x;
         i < (size_t)ND * KD; i += stride) {
        {
            size_t r = i / KD, k = i % KD;
            g_Wd[i] = (k < (ARNN + E)) ? dWih[r * (ARNN + E) + k]
                                       : dWhh[r * DRNN + (k - (ARNN + E))];
        }
        if (i < (size_t)NA * KA) {
            size_t r = i / KA, k = i % KA;
            g_Wa[i] = (k < (PRE + E)) ? aWih[r * (PRE + E) + k]
                                      : aWhh[r * ARNN + (k - (PRE + E))];
        }
        if (i < NA) g_ba[i] = abih[i] + abhh[i];
        if (i < ND) g_bd[i] = dbih[i] + dbhh[i];
        if (i < (size_t)ARNN * ADIM) {
            size_t k = i / ADIM, d = i % ADIM;
            g_qWt[i] = qW[d * ARNN + k];
        }
        if (i < (size_t)(DRNN + E) * 81) {
            size_t j = i / 81, k = i % 81;
            g_pgW[i] = (k < 80) ? projW[k * (DRNN + E) + j] : gateW[j];
        }
        // ---- state init (was zero_state) ----
        if (i < (size_t)B * ARNN) g_ac[i] = 0.f;
        if (i < (size_t)B * DRNN) g_dc[i] = 0.f;
        if (i < (size_t)B * TIN) { g_aw[i] = 0.f; g_awc[i] = 0.f; }
        if (i < (size_t)B * KD) g_cinD[i] = 0.f;
        if (i < (size_t)B * KA) {
            int b = (int)(i / KA), j = (int)(i % KA);
            g_cinA[i] = (j < PRE) ? g_xs[(size_t)b * PRE + j] : 0.f;
        }
    }
}

// ---------- precompute GEMM (prenet / pmem): C = act(A@W^T) ------------
__global__ __launch_bounds__(256) void gemm32(const float* __restrict__ A,
                                              const float* __restrict__ W,
                                              float* __restrict__ C,
                                              int N, int K, int relu) {
    __shared__ float As[32][33];
    __shared__ float Ws[32][33];
    int tid = threadIdx.x;
    int n0 = blockIdx.x * 32, m0 = blockIdx.y * 32;
    int tm = (tid >> 4) << 1, tn = (tid & 15) << 1;
    float a00 = 0.f, a01 = 0.f, a10 = 0.f, a11 = 0.f;
    for (int kt = 0; kt < K; kt += 32) {
#pragma unroll
        for (int i = 0; i < 4; i++) {
            int id = tid + i * 256;
            int r = id >> 5, kk = id & 31;
            int k = kt + kk;
            As[r][kk] = (k < K) ? A[(size_t)(m0 + r) * K + k] : 0.f;
            Ws[r][kk] = (k < K) ? W[(size_t)(n0 + r) * K + k] : 0.f;
        }
        __syncthreads();
#pragma unroll
        for (int kk = 0; kk < 32; kk++) {
            float x0 = As[tm][kk], x1 = As[tm + 1][kk];
            float y0 = Ws[tn][kk], y1 = Ws[tn + 1][kk];
            a00 += x0 * y0; a01 += x0 * y1;
            a10 += x1 * y0; a11 += x1 * y1;
        }
        __syncthreads();
    }
    if (relu) {
        a00 = fmaxf(a00, 0.f); a01 = fmaxf(a01, 0.f);
        a10 = fmaxf(a10, 0.f); a11 = fmaxf(a11, 0.f);
    }
    size_t o = (size_t)(m0 + tm) * N + n0 + tn;
    C[o] = a00; C[o + 1] = a01;
    C[o + N] = a10; C[o + N + 1] = a11;
}

// ---------------- tf32 mma.m16n8k8 helper ------------------------------
__device__ __forceinline__ void mma8(float* d, const float* a, const float* b) {
    asm volatile(
        "mma.sync.aligned.m16n8k8.row.col.f32.tf32.tf32.f32 "
        "{%0,%1,%2,%3},{%4,%5,%6,%7},{%8,%9},{%0,%1,%2,%3};"
        : "+f"(d[0]), "+f"(d[1]), "+f"(d[2]), "+f"(d[3])
        : "r"(__float_as_uint(a[0])), "r"(__float_as_uint(a[1])),
          "r"(__float_as_uint(a[2])), "r"(__float_as_uint(a[3])),
          "r"(__float_as_uint(b[0])), "r"(__float_as_uint(b[1])));
}

// ---------------- persistent-kernel GEMM phase (tf32 mma) ---------------
// Partial C[32][Ntot] at (n0, k in [k0,k0+kl)), fragments fed straight from
// global memory (no smem): per warp-lane, A/B fragment elements are direct
// LDG; b0/b1 (k, k+4) share a 32B sector so L2 traffic == weight bytes.
// Warp layout: mh = w&1 selects m-half (16 rows), wn = w>>1 covers 32 n.
__device__ __forceinline__ void gemm_mma(const float* __restrict__ A,
                                         const float* __restrict__ W,
                                         float* __restrict__ Cp, int Ntot,
                                         int n0, int k0, int kl, int K) {
    int tid = threadIdx.x;
    int w = tid >> 5, lane = tid & 31;
    int g = lane >> 2, t = lane & 3;
    int mh = w & 1, wn = w >> 1;
    const float* Ar0 = A + (size_t)(mh * 16 + g) * K;
    const float* Ar1 = Ar0 + (size_t)8 * K;
    const float* Wr0 = W + (size_t)(n0 + wn * 32 + g) * K;

    float acc[4][4];
#pragma unroll
    for (int nt = 0; nt < 4; nt++)
#pragma unroll
        for (int r = 0; r < 4; r++) acc[nt][r] = 0.f;

    int kend = k0 + kl;
    float a[4], b[4][2];
    // preload first kstep
    a[0] = Ar0[k0 + t];     a[1] = Ar1[k0 + t];
    a[2] = Ar0[k0 + t + 4]; a[3] = Ar1[k0 + t + 4];
#pragma unroll
    for (int nt = 0; nt < 4; nt++) {
        const float* wr = Wr0 + (size_t)(nt * 8) * K;
        b[nt][0] = wr[k0 + t];
        b[nt][1] = wr[k0 + t + 4];
    }
    for (int kk = k0; kk < kend; kk += 8) {
        float na[4], nb[4][2];
        int kn = kk + 8;
        if (kn < kend) {
            na[0] = Ar0[kn + t];     na[1] = Ar1[kn + t];
            na[2] = Ar0[kn + t + 4]; na[3] = Ar1[kn + t + 4];
#pragma unroll
            for (int nt = 0; nt < 4; nt++) {
                const float* wr = Wr0 + (size_t)(nt * 8) * K;
                nb[nt][0] = wr[kn + t];
                nb[nt][1] = wr[kn + t + 4];
            }
        }
#pragma unroll
        for (int nt = 0; nt < 4; nt++) mma8(acc[nt], a, b[nt]);
        if (kn < kend) {
#pragma unroll
            for (int r = 0; r < 4; r++) a[r] = na[r];
#pragma unroll
            for (int nt = 0; nt < 4; nt++) {
                b[nt][0] = nb[nt][0];
                b[nt][1] = nb[nt][1];
            }
        }
    }
    // epilogue: c0=(g,2t), c1=(g,2t+1), c2=(g+8,2t), c3=(g+8,2t+1)
    int mrow = mh * 16 + g;
#pragma unroll
    for (int nt = 0; nt < 4; nt++) {
        int col = n0 + wn * 32 + nt * 8 + 2 * t;
        float2 lo = make_float2(acc[nt][0], acc[nt][1]);
        float2 hi = make_float2(acc[nt][2], acc[nt][3]);
        *(float2*)(Cp + (size_t)mrow * Ntot + col) = lo;
        *(float2*)(Cp + (size_t)(mrow + 8) * Ntot + col) = hi;
    }
}

// --------------------------- persistent kernel -------------------------
__global__ __launch_bounds__(256) void decoder_loop(const float* __restrict__ memory,
                                                    const int* __restrict__ mlen,
                                                    const float* __restrict__ convW,
                                                    const float* __restrict__ convb,
                                                    const float* __restrict__ locW,
                                                    const float* __restrict__ vW,
                                                    const float* __restrict__ projb,
                                                    const float* __restrict__ gateb,
                                                    float* __restrict__ out) {
    __shared__ __align__(16) float smem[10752];
    int bid = blockIdx.x, tid = threadIdx.x;

    for (int t = 0; t < TOUT; t++) {
        // ---------------- P1: attention GEMM (144 blocks, tf32 mma) -------
        if (bid < 24 * SKA) {
            int nt = bid % 24, ks = bid / 24;
            int k0 = ks * KPB_A;
            int kl = (KA - k0 < KPB_A) ? (KA - k0) : KPB_A;
            gemm_mma(g_cinA, g_Wa, g_gAp + (size_t)ks * B * NA, NA,
                     nt * 128, k0, kl, KA);
        }
        gsync();

        // -------- P2: att cell update + q partial (128 blocks) ------------
        if (bid < 128) {
            float* sAh  = smem;
            float* sRed = smem + 256;
            int b = bid >> 2, qt = bid & 3;
            int j = qt * 256 + tid;
            float gi = g_ba[j], gf = g_ba[ARNN + j], gg = g_ba[2 * ARNN + j];
#pragma unroll
            for (int s = 0; s < SKA; s++) {
                const float* gp = g_gAp + ((size_t)s * B + b) * NA;
                gi += gp[j]; gf += gp[ARNN + j]; gg += gp[2 * ARNN + j];
            }
            float c = sigf(gf) * g_ac[b * ARNN + j] + sigf(gi) * tanhf(gg);
            g_ac[b * ARNN + j] = c;
            g_cinA[b * KA + (PRE + E) + j] = c;   // next-step Whh input
            g_cinD[b * KD + j] = c;               // this-step decoder input
            sAh[tid] = c;
            __syncthreads();
            int d = tid & (ADIM - 1), half = tid >> 7;
            const float* qw = g_qWt + ((size_t)(qt * 256 + half * 128)) * ADIM + d;
            float acc = 0.f;
#pragma unroll 8
            for (int k = 0; k < 128; k++)
                acc += sAh[half * 128 + k] * qw[(size_t)k * ADIM];
            sRed[tid] = acc;
            __syncthreads();
            if (tid < ADIM)
                g_qp[(b * 4 + qt) * ADIM + tid] = sRed[tid] + sRed[128 + tid];
        }
        gsync();

        // -------- P3: location conv + energies (128 blocks) ---------------
        if (bid < 128) {
            int b = bid >> 2, tq = bid & 3;
            int t0 = tq * 128;
            int len = mlen[b];
            if (t0 < len) {
                float* sQ   = smem;          // 128
                float* sV   = smem + 128;    // 128
                float* sAw  = smem + 256;    // 158
                float* sAwc = smem + 414;    // 158
                float* sCW  = smem + 572;    // 1984
                float* sLW  = smem + 2556;   // 4096 [f][d]
                float* sLR  = smem + 6652;   // 4096 [tl][f]
                if (tid < 128) {
                    float q = 0.f;
#pragma unroll
                    for (int p = 0; p < 4; p++) q += g_qp[(b * 4 + p) * ADIM + tid];
                    sQ[tid] = q;
                    sV[tid] = vW[tid];
                }
                for (int i = tid; i < NF * 2 * KS; i += 256) sCW[i] = convW[i];
                for (int i = tid; i < NF * ADIM; i += 256) {
                    int f = i & 31, d = i >> 5;
                    sLW[f * ADIM + d] = locW[d * NF + f];
                }
                for (int i = tid; i < 158; i += 256) {
                    int tt = t0 - (KS / 2) + i;
                    bool ok = (tt >= 0 && tt < TIN);
                    sAw[i]  = ok ? g_aw[b * TIN + tt]  : 0.f;
                    sAwc[i] = ok ? g_awc[b * TIN + tt] : 0.f;
                }
                __syncthreads();
                int tmax = len - t0; if (tmax > 128) tmax = 128;
                for (int i = tid; i < tmax * NF; i += 256) {
                    int tl = i >> 5, f = i & 31;
                    float acc = convb[f];
                    const float* w0 = sCW + f * 2 * KS;
                    const float* w1 = w0 + KS;
#pragma unroll
                    for (int k = 0; k < KS; k++)
                        acc += w0[k] * sAw[tl + k] + w1[k] * sAwc[tl + k];
                    sLR[tl * NF + f] = acc;
                }
                __syncthreads();
                int w = tid >> 5, lane = tid & 31;
                for (int tl = w; tl < tmax; tl += 8) {
                    float x0 = sQ[lane]       + g_pmem[((size_t)b * TIN + t0 + tl) * ADIM + lane];
                    float x1 = sQ[lane + 32]  + g_pmem[((size_t)b * TIN + t0 + tl) * ADIM + lane + 32];
                    float x2 = sQ[lane + 64]  + g_pmem[((size_t)b * TIN + t0 + tl) * ADIM + lane + 64];
                    float x3 = sQ[lane + 96]  + g_pmem[((size_t)b * TIN + t0 + tl) * ADIM + lane + 96];
                    const float* lr = sLR + tl * NF;
#pragma unroll
                    for (int f = 0; f < NF; f++) {
                        float r = lr[f];
                        x0 += r * sLW[f * ADIM + lane];
                        x1 += r * sLW[f * ADIM + lane + 32];
                        x2 += r * sLW[f * ADIM + lane + 64];
                        x3 += r * sLW[f * ADIM + lane + 96];
                    }
                    float e = tanhf(x0) * sV[lane] + tanhf(x1) * sV[lane + 32]
                            + tanhf(x2) * sV[lane + 64] + tanhf(x3) * sV[lane + 96];
#pragma unroll
                    for (int o = 16; o > 0; o >>= 1)
                        e += __shfl_down_sync(0xffffffffu, e, o);
                    if (lane == 0) g_en[b * TIN + t0 + tl] = e;
                }
            }
        }
        gsync();

        // -------- P4: softmax + context + align out (128 blocks) ----------
        if (bid < 128) {
            float* sAw  = smem;          // 512
            float* sRed = smem + 512;    // 256
            int b = bid >> 2, ec = bid & 3;
            int e0 = ec * 144;
            int len = mlen[b];
            float v1 = (tid < len) ? g_en[b * TIN + tid] : -1e30f;
            float v2 = (tid + 256 < len) ? g_en[b * TIN + tid + 256] : -1e30f;
            sRed[tid] = fmaxf(v1, v2);
            __syncthreads();
            for (int s = 128; s > 0; s >>= 1) {
                if (tid < s) sRed[tid] = fmaxf(sRed[tid], sRed[tid + s]);
                __syncthreads();
            }
            float mx = sRed[0];
            __syncthreads();
            float x1 = (tid < len) ? expf(v1 - mx) : 0.f;
            float x2 = (tid + 256 < len) ? expf(v2 - mx) : 0.f;
            sRed[tid] = x1 + x2;
            __syncthreads();
            for (int s = 128; s > 0; s >>= 1) {
                if (tid < s) sRed[tid] += sRed[tid + s];
                __syncthreads();
            }
            float inv = 1.f / sRed[0];
            float aw1 = x1 * inv, aw2 = x2 * inv;
            sAw[tid] = aw1;
            sAw[tid + 256] = aw2;
            if (ec == 0) {
                g_aw[b * TIN + tid] = aw1;
                g_aw[b * TIN + tid + 256] = aw2;
                g_awc[b * TIN + tid] += aw1;
                g_awc[b * TIN + tid + 256] += aw2;
                out[ALIGN_OFF + ((size_t)b * TOUT + t) * TIN + tid] = aw1;
                out[ALIGN_OFF + ((size_t)b * TOUT + t) * TIN + tid + 256] = aw2;
            }
            __syncthreads();
            if (tid < 144) {
                int e = e0 + tid;
                const float* mp = memory + (size_t)b * TIN * E + e;
                float ac0 = 0.f, ac1 = 0.f, ac2 = 0.f, ac3 = 0.f;
                int tt = 0;
                for (; tt + 4 <= len; tt += 4) {
                    ac0 += sAw[tt]     * mp[(size_t)tt * E];
                    ac1 += sAw[tt + 1] * mp[(size_t)(tt + 1) * E];
                    ac2 += sAw[tt + 2] * mp[(size_t)(tt + 2) * E];
                    ac3 += sAw[tt + 3] * mp[(size_t)(tt + 3) * E];
                }
                for (; tt < len; tt++) ac0 += sAw[tt] * mp[(size_t)tt * E];
                float acc = (ac0 + ac1) + (ac2 + ac3);
                g_cinA[b * KA + PRE + e] = acc;    // next-step att ctx
                g_cinD[b * KD + ARNN + e] = acc;   // this-step dec ctx
            }
        }
        gsync();

        // ---------------- P5: decoder GEMM (128 blocks, tf32 mma) ---------
        if (bid < 32 * SKD) {
            int nt = bid % 32, ks = bid / 32;
            gemm_mma(g_cinD, g_Wd, g_gDp + (size_t)ks * B * ND, ND,
                     nt * 128, ks * KPB_D, KPB_D, KD);
        }
        gsync();

        // ------ P6: dec cell update + mel/gate proj + next xt (32 blocks) --
        if (bid < 32) {
            float* sIn   = smem;          // 1600
            float* sPart = smem + 1600;   // 243
            int b = bid;
#pragma unroll
            for (int r = 0; r < 4; r++) {
                int j = tid + r * 256;
                float gi = g_bd[j], gf = g_bd[DRNN + j],
                      gg = g_bd[2 * DRNN + j], go = g_bd[3 * DRNN + j];
#pragma unroll
                for (int s = 0; s < SKD; s++) {
                    const float* gp = g_gDp + ((size_t)s * B + b) * ND;
                    gi += gp[j]; gf += gp[DRNN + j];
                    gg += gp[2 * DRNN + j]; go += gp[3 * DRNN + j];
                }
                float c = sigf(gf) * g_dc[b * DRNN + j] + sigf(gi) * tanhf(gg);
                g_dc[b * DRNN + j] = c;
                float h = sigf(go) * tanhf(c);
                sIn[j] = h;
                g_cinD[b * KD + (ARNN + E) + j] = h;   // next-step Whh input
            }
#pragma unroll
            for (int r = 0; r < 3; r++) {
                int j = tid + r * 256;
                if (j < E) sIn[DRNN + j] = g_cinD[b * KD + ARNN + j];
            }
            __syncthreads();
            if (tid < 243) {
                int part = tid / 81, o = tid - part * 81;
                int j0 = part * 534;
                int j1 = (part == 2) ? 1600 : j0 + 534;
                float acc = 0.f;
                for (int j = j0; j < j1; j++)
                    acc += sIn[j] * g_pgW[(size_t)j * 81 + o];
                sPart[tid] = acc;
            }
            __syncthreads();
            if (tid < 81) {
                float tot = sPart[tid] + sPart[81 + tid] + sPart[162 + tid];
                if (tid < 80) out[((size_t)b * NMEL + tid) * TOUT + t] = tot + projb[tid];
                else          out[GATE_OFF + (size_t)b * TOUT + t] = tot + gateb[0];
            }
            if (t + 1 < TOUT)
                g_cinA[b * KA + tid] = g_xs[((size_t)(t + 1) * B + b) * PRE + tid];
        }
        gsync();
    }
}

// ------------------------------ host ----------------------------------
extern "C" void kernel_launch(void* const* d_in, const int* in_sizes, int n_in,
                              void* d_out, int out_size) {
    const float* memory = (const float*)d_in[0];
    const float* dec    = (const float*)d_in[1];
    const float* pW1    = (const float*)d_in[2];
    const float* pW2    = (const float*)d_in[3];
    const float* aWih   = (const float*)d_in[4];
    const float* aWhh   = (const float*)d_in[5];
    const float* abih   = (const float*)d_in[6];
    const float* abhh   = (const float*)d_in[7];
    const float* qW     = (const float*)d_in[8];
    const float* memW   = (const float*)d_in[9];
    const float* convW  = (const float*)d_in[10];
    const float* convb  = (const float*)d_in[11];
    const float* locW   = (const float*)d_in[12];
    const float* vW     = (const float*)d_in[13];
    const float* dWih   = (const float*)d_in[14];
    const float* dWhh   = (const float*)d_in[15];
    const float* dbih   = (const float*)d_in[16];
    const float* dbhh   = (const float*)d_in[17];
    const float* projW  = (const float*)d_in[18];
    const float* projb  = (const float*)d_in[19];
    const float* gateW  = (const float*)d_in[20];
    const float* gateb  = (const float*)d_in[21];
    const int*   mlen   = (const int*)d_in[22];
    float* out = (float*)d_out;

    void* p;
    float *di, *h1, *xs, *pmem;
    cudaGetSymbolAddress(&p, g_di);   di   = (float*)p;
    cudaGetSymbolAddress(&p, g_h1);   h1   = (float*)p;
    cudaGetSymbolAddress(&p, g_xs);   xs   = (float*)p;
    cudaGetSymbolAddress(&p, g_pmem); pmem = (float*)p;

    // ---- precompute: exactly 5 launches (decoder_loop is launch #6) ----
    build_di<<<(TOUT * B * NMEL + 255) / 256, 256>>>(dec);
    gemm32<<<dim3(PRE / 32, TOUT * B / 32), 256>>>(di, pW1, h1, PRE, NMEL, 1);
    gemm32<<<dim3(PRE / 32, TOUT * B / 32), 256>>>(h1, pW2, xs, PRE, PRE, 1);
    gemm32<<<dim3(ADIM / 32, B * TIN / 32), 256>>>(memory, memW, pmem, ADIM, E, 0);
    pack_weights<<<2048, 256>>>(aWih, aWhh, abih, abhh, dWih, dWhh, dbih, dbhh,
                                qW, projW, gateW);

    // ---- whole 400-step recurrence: one persistent kernel ----
    decoder_loop<<<NBLK, 256>>>(memory, mlen, convW, convb, locW, vW,
                                projb, gateb, out);
}

// round 9
// speedup vs baseline: 1.3234x; 1.2659x over previous
#include <cuda_runtime.h>
#include <math.h>
#include <stdint.h>
#include <stddef.h>

#define B 32
#define TIN 512
#define E 576
#define TOUT 400
#define NMEL 80
#define PRE 256
#define ARNN 1024
#define DRNN 1024
#define ADIM 128
#define NF 32
#define KS 31

#define KA (PRE + E + ARNN)    /* 1856 : [xt | ctx | ah] */
#define NA (3 * ARNN)          /* 3072 : gates i,f,g (o-gate dead: ah=ac) */
#define KD (ARNN + E + DRNN)   /* 2624 : [ah | ctx | dh] */
#define ND (4 * DRNN)          /* 4096 */

#define NBLK 148
#define SKA 6                  /* att split-K: 24 ntiles x 6 = 144 blocks */
#define SKD 4                  /* dec split-K: 32 ntiles x 4 = 128 blocks */
#define KPB_A 320              /* splits {320x5, 256}, all /32 */
#define KPB_D 672              /* splits {672x3, 608}, all /32 */

#define GATE_OFF  ((size_t)B * NMEL * TOUT)
#define ALIGN_OFF (GATE_OFF + (size_t)B * TOUT)

// --------------------------- device scratch ---------------------------
__device__ float g_di[(size_t)TOUT * B * NMEL];
__device__ float g_h1[(size_t)TOUT * B * PRE];
__device__ float g_xs[(size_t)TOUT * B * PRE];
__device__ float g_pmem[(size_t)B * TIN * ADIM];
__device__ float g_Wa[(size_t)NA * KA];
__device__ float g_Wd[(size_t)ND * KD];
__device__ float g_ba[NA];
__device__ float g_bd[ND];
__device__ float g_qWt[(size_t)ARNN * ADIM];        // [k][d]
__device__ float g_pgW[(size_t)81 * (DRNN + E)];    // [o][j], o=80 -> gate row
__device__ float g_cinA[B * KA];                    // tf32-rounded GEMM input
__device__ float g_cinD[B * KD];                    // tf32-rounded GEMM input
__device__ float g_ctx[B * E];                      // full-precision ctx for proj
__device__ float g_ac[B * ARNN];
__device__ float g_dc[B * DRNN];
__device__ float g_aw[B * TIN];
__device__ float g_awc[B * TIN];
__device__ float g_qp[B * 4 * ADIM];
__device__ float g_en[B * TIN];
__device__ float g_gAp[(size_t)SKA * B * NA];
__device__ float g_gDp[(size_t)SKD * B * ND];

__device__ unsigned g_cnt = 0;
__device__ unsigned g_gen = 0;

__device__ __forceinline__ float sigf(float x) { return 1.f / (1.f + expf(-x)); }

// round-to-nearest tf32 (unbiased; keeps mma numerics honest)
__device__ __forceinline__ float tf32r(float x) {
    unsigned u;
    asm("cvt.rna.tf32.f32 %0, %1;" : "=r"(u) : "f"(x));
    return __uint_as_float(u);
}

// --------------------------- grid barrier (CG-style) -------------------
__device__ __forceinline__ void gsync() {
    __syncthreads();
    if (threadIdx.x == 0) {
        unsigned gen = g_gen;
        unsigned old;
        asm volatile("atom.acq_rel.gpu.global.add.u32 %0, [%1], 1;"
                     : "=r"(old) : "l"(&g_cnt) : "memory");
        if (old == NBLK - 1) {
            g_cnt = 0;   // ordered before the release store below
            asm volatile("st.release.gpu.global.u32 [%0], %1;"
                         :: "l"(&g_gen), "r"(gen + 1) : "memory");
        } else {
            unsigned v;
            do {
                __nanosleep(64);
                asm volatile("ld.acquire.gpu.global.u32 %0, [%1];"
                             : "=r"(v) : "l"(&g_gen) : "memory");
            } while (v == gen);
        }
    }
    __syncthreads();
}

// --------------------------- precompute kernels ------------------------
__global__ void build_di(const float* __restrict__ dec) {
    int i = blockIdx.x * 256 + threadIdx.x;
    if (i >= TOUT * B * NMEL) return;
    int k = i % NMEL;
    int r = i / NMEL;
    int b = r % B;
    int t = r / B;
    g_di[i] = (t == 0) ? 0.f : dec[((size_t)b * TOUT + (t - 1)) * NMEL + k];
}

// pack weights (tf32-rounded for mma operands) + zero state (xs ready)
__global__ void pack_weights(const float* __restrict__ aWih, const float* __restrict__ aWhh,
                             const float* __restrict__ abih, const float* __restrict__ abhh,
                             const float* __restrict__ dWih, const float* __restrict__ dWhh,
                             const float* __restrict__ dbih, const float* __restrict__ dbhh,
                             const float* __restrict__ qW,   const float* __restrict__ projW,
                             const float* __restrict__ gateW) {
    size_t stride = (size_t)gridDim.x * blockDim.x;
    for (size_t i = (size_t)blockIdx.x * blockDim.x + threadIdx.x;
         i < (size_t)ND * KD; i += stride) {
        {
            size_t r = i / KD, k = i % KD;
            float v = (k < (ARNN + E)) ? dWih[r * (ARNN + E) + k]
                                       : dWhh[r * DRNN + (k - (ARNN + E))];
            g_Wd[i] = tf32r(v);
        }
        if (i < (size_t)NA * KA) {
            size_t r = i / KA, k = i % KA;
            float v = (k < (PRE + E)) ? aWih[r * (PRE + E) + k]
                                      : aWhh[r * ARNN + (k - (PRE + E))];
            g_Wa[i] = tf32r(v);
        }
        if (i < NA) g_ba[i] = abih[i] + abhh[i];
        if (i < ND) g_bd[i] = dbih[i] + dbhh[i];
        if (i < (size_t)ARNN * ADIM) {
            size_t k = i / ADIM, d = i % ADIM;
            g_qWt[i] = qW[d * ARNN + k];
        }
        if (i < (size_t)81 * (DRNN + E)) {
            size_t o = i / (DRNN + E), j = i % (DRNN + E);
            g_pgW[i] = (o < 80) ? projW[o * (DRNN + E) + j] : gateW[j];
        }
        // ---- state init ----
        if (i < (size_t)B * ARNN) g_ac[i] = 0.f;
        if (i < (size_t)B * DRNN) g_dc[i] = 0.f;
        if (i < (size_t)B * TIN) { g_aw[i] = 0.f; g_awc[i] = 0.f; }
        if (i < (size_t)B * KD) g_cinD[i] = 0.f;
        if (i < (size_t)B * KA) {
            int b = (int)(i / KA), j = (int)(i % KA);
            g_cinA[i] = (j < PRE) ? tf32r(g_xs[(size_t)b * PRE + j]) : 0.f;
        }
    }
}

// ---------- precompute GEMM (prenet / pmem): C = act(A@W^T) ------------
__global__ __launch_bounds__(256) void gemm32(const float* __restrict__ A,
                                              const float* __restrict__ W,
                                              float* __restrict__ C,
                                              int N, int K, int relu) {
    __shared__ float As[32][33];
    __shared__ float Ws[32][33];
    int tid = threadIdx.x;
    int n0 = blockIdx.x * 32, m0 = blockIdx.y * 32;
    int tm = (tid >> 4) << 1, tn = (tid & 15) << 1;
    float a00 = 0.f, a01 = 0.f, a10 = 0.f, a11 = 0.f;
    for (int kt = 0; kt < K; kt += 32) {
#pragma unroll
        for (int i = 0; i < 4; i++) {
            int id = tid + i * 256;
            int r = id >> 5, kk = id & 31;
            int k = kt + kk;
            As[r][kk] = (k < K) ? A[(size_t)(m0 + r) * K + k] : 0.f;
            Ws[r][kk] = (k < K) ? W[(size_t)(n0 + r) * K + k] : 0.f;
        }
        __syncthreads();
#pragma unroll
        for (int kk = 0; kk < 32; kk++) {
            float x0 = As[tm][kk], x1 = As[tm + 1][kk];
            float y0 = Ws[tn][kk], y1 = Ws[tn + 1][kk];
            a00 += x0 * y0; a01 += x0 * y1;
            a10 += x1 * y0; a11 += x1 * y1;
        }
        __syncthreads();
    }
    if (relu) {
        a00 = fmaxf(a00, 0.f); a01 = fmaxf(a01, 0.f);
        a10 = fmaxf(a10, 0.f); a11 = fmaxf(a11, 0.f);
    }
    size_t o = (size_t)(m0 + tm) * N + n0 + tn;
    C[o] = a00; C[o + 1] = a01;
    C[o + N] = a10; C[o + N + 1] = a11;
}

// ---------------- tf32 mma.m16n8k8 helper ------------------------------
__device__ __forceinline__ void mma8(float* d, const float* a, const float* b) {
    asm volatile(
        "mma.sync.aligned.m16n8k8.row.col.f32.tf32.tf32.f32 "
        "{%0,%1,%2,%3},{%4,%5,%6,%7},{%8,%9},{%0,%1,%2,%3};"
        : "+f"(d[0]), "+f"(d[1]), "+f"(d[2]), "+f"(d[3])
        : "r"(__float_as_uint(a[0])), "r"(__float_as_uint(a[1])),
          "r"(__float_as_uint(a[2])), "r"(__float_as_uint(a[3])),
          "r"(__float_as_uint(b[0])), "r"(__float_as_uint(b[1])));
}

// ------------- smem-staged tf32 GEMM phase: C[32][128] partial ----------
// Tiles staged in smem with 36-float row pitch: fragment LDS bank index is
// (4g + t + c) mod 32 -> conflict-free. Coalesced float4 global loads.
__device__ __forceinline__ void gemm_mma(const float* __restrict__ A,
                                         const float* __restrict__ W,
                                         float* __restrict__ Cp, int Ntot,
                                         int n0, int k0, int kl, int K,
                                         float* sm) {
    float* sA = sm;            // [32][36]
    float* sW = sm + 32 * 36;  // [128][36]
    int tid = threadIdx.x;
    int w = tid >> 5, lane = tid & 31;
    int g = lane >> 2, t = lane & 3;
    int mh = w & 1, wn = w >> 1;

    float acc[4][4];
#pragma unroll
    for (int nt = 0; nt < 4; nt++)
#pragma unroll
        for (int r = 0; r < 4; r++) acc[nt][r] = 0.f;

    int ar = tid >> 3, aq = tid & 7;   // A tile loader coords
    for (int kc = k0; kc < k0 + kl; kc += 32) {
        __syncthreads();
        {
            float4 v = *(const float4*)(A + (size_t)ar * K + kc + aq * 4);
            *(float4*)(sA + ar * 36 + aq * 4) = v;
        }
#pragma unroll
        for (int i = 0; i < 4; i++) {
            int id = tid + i * 256;
            int r = id >> 3, q = id & 7;
            float4 v = *(const float4*)(W + (size_t)(n0 + r) * K + kc + q * 4);
            *(float4*)(sW + r * 36 + q * 4) = v;
        }
        __syncthreads();
#pragma unroll
        for (int kk = 0; kk < 32; kk += 8) {
            float a[4];
            a[0] = sA[(mh * 16 + g) * 36 + kk + t];
            a[1] = sA[(mh * 16 + g + 8) * 36 + kk + t];
            a[2] = sA[(mh * 16 + g) * 36 + kk + t + 4];
            a[3] = sA[(mh * 16 + g + 8) * 36 + kk + t + 4];
#pragma unroll
            for (int nt = 0; nt < 4; nt++) {
                float b[2];
                int rw = wn * 32 + nt * 8 + g;
                b[0] = sW[rw * 36 + kk + t];
                b[1] = sW[rw * 36 + kk + t + 4];
                mma8(acc[nt], a, b);
            }
        }
    }
    int mrow = mh * 16 + g;
#pragma unroll
    for (int nt = 0; nt < 4; nt++) {
        int col = n0 + wn * 32 + nt * 8 + 2 * t;
        float2 lo = make_float2(acc[nt][0], acc[nt][1]);
        float2 hi = make_float2(acc[nt][2], acc[nt][3]);
        *(float2*)(Cp + (size_t)mrow * Ntot + col) = lo;
        *(float2*)(Cp + (size_t)(mrow + 8) * Ntot + col) = hi;
    }
}

// --------------------------- persistent kernel -------------------------
__global__ __launch_bounds__(256) void decoder_loop(const float* __restrict__ memory,
                                                    const int* __restrict__ mlen,
                                                    const float* __restrict__ convW,
                                                    const float* __restrict__ convb,
                                                    const float* __restrict__ locW,
                                                    const float* __restrict__ vW,
                                                    const float* __restrict__ projb,
                                                    const float* __restrict__ gateb,
                                                    float* __restrict__ out) {
    __shared__ __align__(16) float smem[10752];
    int bid = blockIdx.x, tid = threadIdx.x;

    for (int t = 0; t < TOUT; t++) {
        // ---------------- P1: attention GEMM (144 blocks) -----------------
        if (bid < 24 * SKA) {
            int nt = bid % 24, ks = bid / 24;
            int k0 = ks * KPB_A;
            int kl = (KA - k0 < KPB_A) ? (KA - k0) : KPB_A;
            gemm_mma(g_cinA, g_Wa, g_gAp + (size_t)ks * B * NA, NA,
                     nt * 128, k0, kl, KA, smem);
        }
        gsync();

        // -------- P2: att cell update + q partial (128 blocks) ------------
        if (bid < 128) {
            float* sAh  = smem;
            float* sRed = smem + 256;
            int b = bid >> 2, qt = bid & 3;
            int j = qt * 256 + tid;
            float gi = g_ba[j], gf = g_ba[ARNN + j], gg = g_ba[2 * ARNN + j];
#pragma unroll
            for (int s = 0; s < SKA; s++) {
                const float* gp = g_gAp + ((size_t)s * B + b) * NA;
                gi += gp[j]; gf += gp[ARNN + j]; gg += gp[2 * ARNN + j];
            }
            float c = sigf(gf) * g_ac[b * ARNN + j] + sigf(gi) * tanhf(gg);
            g_ac[b * ARNN + j] = c;
            float cr = tf32r(c);
            g_cinA[b * KA + (PRE + E) + j] = cr;   // next-step Whh input
            g_cinD[b * KD + j] = cr;               // this-step decoder input
            sAh[tid] = c;
            __syncthreads();
            int d = tid & (ADIM - 1), half = tid >> 7;
            const float* qw = g_qWt + ((size_t)(qt * 256 + half * 128)) * ADIM + d;
            float acc = 0.f;
#pragma unroll 8
            for (int k = 0; k < 128; k++)
                acc += sAh[half * 128 + k] * qw[(size_t)k * ADIM];
            sRed[tid] = acc;
            __syncthreads();
            if (tid < ADIM)
                g_qp[(b * 4 + qt) * ADIM + tid] = sRed[tid] + sRed[128 + tid];
        }
        gsync();

        // -------- P3: location conv + energies (128 blocks) ---------------
        if (bid < 128) {
            int b = bid >> 2, tq = bid & 3;
            int t0 = tq * 128;
            int len = mlen[b];
            if (t0 < len) {
                float* sQ   = smem;          // 128
                float* sV   = smem + 128;    // 128
                float* sAw  = smem + 256;    // 158
                float* sAwc = smem + 414;    // 158
                float* sCW  = smem + 572;    // 1984
                float* sLW  = smem + 2556;   // 4096 [f][d]
                float* sLR  = smem + 6652;   // 4096 [tl][f]
                if (tid < 128) {
                    float q = 0.f;
#pragma unroll
                    for (int p = 0; p < 4; p++) q += g_qp[(b * 4 + p) * ADIM + tid];
                    sQ[tid] = q;
                    sV[tid] = vW[tid];
                }
                for (int i = tid; i < NF * 2 * KS; i += 256) sCW[i] = convW[i];
                for (int i = tid; i < NF * ADIM; i += 256) {
                    int f = i & 31, d = i >> 5;
                    sLW[f * ADIM + d] = locW[d * NF + f];
                }
                for (int i = tid; i < 158; i += 256) {
                    int tt = t0 - (KS / 2) + i;
                    bool ok = (tt >= 0 && tt < TIN);
                    sAw[i]  = ok ? g_aw[b * TIN + tt]  : 0.f;
                    sAwc[i] = ok ? g_awc[b * TIN + tt] : 0.f;
                }
                __syncthreads();
                int tmax = len - t0; if (tmax > 128) tmax = 128;
                for (int i = tid; i < tmax * NF; i += 256) {
                    int tl = i >> 5, f = i & 31;
                    float acc = convb[f];
                    const float* w0 = sCW + f * 2 * KS;
                    const float* w1 = w0 + KS;
#pragma unroll
                    for (int k = 0; k < KS; k++)
                        acc += w0[k] * sAw[tl + k] + w1[k] * sAwc[tl + k];
                    sLR[tl * NF + f] = acc;
                }
                __syncthreads();
                int w = tid >> 5, lane = tid & 31;
                for (int tl = w; tl < tmax; tl += 8) {
                    float x0 = sQ[lane]       + g_pmem[((size_t)b * TIN + t0 + tl) * ADIM + lane];
                    float x1 = sQ[lane + 32]  + g_pmem[((size_t)b * TIN + t0 + tl) * ADIM + lane + 32];
                    float x2 = sQ[lane + 64]  + g_pmem[((size_t)b * TIN + t0 + tl) * ADIM + lane + 64];
                    float x3 = sQ[lane + 96]  + g_pmem[((size_t)b * TIN + t0 + tl) * ADIM + lane + 96];
                    const float* lr = sLR + tl * NF;
#pragma unroll
                    for (int f = 0; f < NF; f++) {
                        float r = lr[f];
                        x0 += r * sLW[f * ADIM + lane];
                        x1 += r * sLW[f * ADIM + lane + 32];
                        x2 += r * sLW[f * ADIM + lane + 64];
                        x3 += r * sLW[f * ADIM + lane + 96];
                    }
                    float e = tanhf(x0) * sV[lane] + tanhf(x1) * sV[lane + 32]
                            + tanhf(x2) * sV[lane + 64] + tanhf(x3) * sV[lane + 96];
#pragma unroll
                    for (int o = 16; o > 0; o >>= 1)
                        e += __shfl_down_sync(0xffffffffu, e, o);
                    if (lane == 0) g_en[b * TIN + t0 + tl] = e;
                }
            }
        }
        gsync();

        // -------- P4: softmax + context + align out (128 blocks) ----------
        if (bid < 128) {
            float* sAw  = smem;          // 512
            float* sRed = smem + 512;    // 256
            int b = bid >> 2, ec = bid & 3;
            int e0 = ec * 144;
            int len = mlen[b];
            float v1 = (tid < len) ? g_en[b * TIN + tid] : -1e30f;
            float v2 = (tid + 256 < len) ? g_en[b * TIN + tid + 256] : -1e30f;
            sRed[tid] = fmaxf(v1, v2);
            __syncthreads();
            for (int s = 128; s > 0; s >>= 1) {
                if (tid < s) sRed[tid] = fmaxf(sRed[tid], sRed[tid + s]);
                __syncthreads();
            }
            float mx = sRed[0];
            __syncthreads();
            float x1 = (tid < len) ? expf(v1 - mx) : 0.f;
            float x2 = (tid + 256 < len) ? expf(v2 - mx) : 0.f;
            sRed[tid] = x1 + x2;
            __syncthreads();
            for (int s = 128; s > 0; s >>= 1) {
                if (tid < s) sRed[tid] += sRed[tid + s];
                __syncthreads();
            }
            float inv = 1.f / sRed[0];
            float aw1 = x1 * inv, aw2 = x2 * inv;
            sAw[tid] = aw1;
            sAw[tid + 256] = aw2;
            if (ec == 0) {
                g_aw[b * TIN + tid] = aw1;
                g_aw[b * TIN + tid + 256] = aw2;
                g_awc[b * TIN + tid] += aw1;
                g_awc[b * TIN + tid + 256] += aw2;
                out[ALIGN_OFF + ((size_t)b * TOUT + t) * TIN + tid] = aw1;
                out[ALIGN_OFF + ((size_t)b * TOUT + t) * TIN + tid + 256] = aw2;
            }
            __syncthreads();
            if (tid < 144) {
                int e = e0 + tid;
                const float* mp = memory + (size_t)b * TIN * E + e;
                float ac[8];
#pragma unroll
                for (int u = 0; u < 8; u++) ac[u] = 0.f;
                int tt = 0;
                for (; tt + 8 <= len; tt += 8) {
#pragma unroll
                    for (int u = 0; u < 8; u++)
                        ac[u] += sAw[tt + u] * mp[(size_t)(tt + u) * E];
                }
                for (; tt < len; tt++) ac[0] += sAw[tt] * mp[(size_t)tt * E];
                float acc = ((ac[0] + ac[1]) + (ac[2] + ac[3]))
                          + ((ac[4] + ac[5]) + (ac[6] + ac[7]));
                g_ctx[b * E + e] = acc;             // full precision for proj
                float cr = tf32r(acc);
                g_cinA[b * KA + PRE + e] = cr;      // next-step att ctx
                g_cinD[b * KD + ARNN + e] = cr;     // this-step dec ctx
            }
        }
        gsync();

        // ---------------- P5: decoder GEMM (128 blocks) -------------------
        if (bid < 32 * SKD) {
            int nt = bid % 32, ks = bid / 32;
            int k0 = ks * KPB_D;
            int kl = (KD - k0 < KPB_D) ? (KD - k0) : KPB_D;
            gemm_mma(g_cinD, g_Wd, g_gDp + (size_t)ks * B * ND, ND,
                     nt * 128, k0, kl, KD, smem);
        }
        gsync();

        // ------ P6: dec cell update + mel/gate proj + next xt (32 blocks) --
        if (bid < 32) {
            float* sIn = smem;            // 1600
            int b = bid;
#pragma unroll
            for (int r = 0; r < 4; r++) {
                int j = tid + r * 256;
                float gi = g_bd[j], gf = g_bd[DRNN + j],
                      gg = g_bd[2 * DRNN + j], go = g_bd[3 * DRNN + j];
#pragma unroll
                for (int s = 0; s < SKD; s++) {
                    const float* gp = g_gDp + ((size_t)s * B + b) * ND;
                    gi += gp[j]; gf += gp[DRNN + j];
                    gg += gp[2 * DRNN + j]; go += gp[3 * DRNN + j];
                }
                float c = sigf(gf) * g_dc[b * DRNN + j] + sigf(gi) * tanhf(gg);
                g_dc[b * DRNN + j] = c;
                float h = sigf(go) * tanhf(c);
                sIn[j] = h;
                g_cinD[b * KD + (ARNN + E) + j] = tf32r(h);  // next-step Whh in
            }
#pragma unroll
            for (int r = 0; r < 3; r++) {
                int j = tid + r * 256;
                if (j < E) sIn[DRNN + j] = g_ctx[b * E + j]; // full-precision ctx
            }
            __syncthreads();
            {
                int w = tid >> 5, lane = tid & 31;
                for (int o = w; o < 81; o += 8) {
                    const float* pw = g_pgW + (size_t)o * (DRNN + E);
                    float acc = 0.f;
#pragma unroll 10
                    for (int j = lane; j < DRNN + E; j += 32)
                        acc += sIn[j] * pw[j];
#pragma unroll
                    for (int off = 16; off > 0; off >>= 1)
                        acc += __shfl_down_sync(0xffffffffu, acc, off);
                    if (lane == 0) {
                        if (o < 80) out[((size_t)b * NMEL + o) * TOUT + t] = acc + projb[o];
                        else        out[GATE_OFF + (size_t)b * TOUT + t] = acc + gateb[0];
                    }
                }
            }
            if (t + 1 < TOUT)
                g_cinA[b * KA + tid] = tf32r(g_xs[((size_t)(t + 1) * B + b) * PRE + tid]);
        }
        gsync();
    }
}

// ------------------------------ host ----------------------------------
extern "C" void kernel_launch(void* const* d_in, const int* in_sizes, int n_in,
                              void* d_out, int out_size) {
    const float* memory = (const float*)d_in[0];
    const float* dec    = (const float*)d_in[1];
    const float* pW1    = (const float*)d_in[2];
    const float* pW2    = (const float*)d_in[3];
    const float* aWih   = (const float*)d_in[4];
    const float* aWhh   = (const float*)d_in[5];
    const float* abih   = (const float*)d_in[6];
    const float* abhh   = (const float*)d_in[7];
    const float* qW     = (const float*)d_in[8];
    const float* memW   = (const float*)d_in[9];
    const float* convW  = (const float*)d_in[10];
    const float* convb  = (const float*)d_in[11];
    const float* locW   = (const float*)d_in[12];
    const float* vW     = (const float*)d_in[13];
    const float* dWih   = (const float*)d_in[14];
    const float* dWhh   = (const float*)d_in[15];
    const float* dbih   = (const float*)d_in[16];
    const float* dbhh   = (const float*)d_in[17];
    const float* projW  = (const float*)d_in[18];
    const float* projb  = (const float*)d_in[19];
    const float* gateW  = (const float*)d_in[20];
    const float* gateb  = (const float*)d_in[21];
    const int*   mlen   = (const int*)d_in[22];
    float* out = (float*)d_out;

    void* p;
    float *di, *h1, *xs, *pmem;
    cudaGetSymbolAddress(&p, g_di);   di   = (float*)p;
    cudaGetSymbolAddress(&p, g_h1);   h1   = (float*)p;
    cudaGetSymbolAddress(&p, g_xs);   xs   = (float*)p;
    cudaGetSymbolAddress(&p, g_pmem); pmem = (float*)p;

    // ---- precompute: 5 launches ----
    build_di<<<(TOUT * B * NMEL + 255) / 256, 256>>>(dec);
    gemm32<<<dim3(PRE / 32, TOUT * B / 32), 256>>>(di, pW1, h1, PRE, NMEL, 1);
    gemm32<<<dim3(PRE / 32, TOUT * B / 32), 256>>>(h1, pW2, xs, PRE, PRE, 1);
    gemm32<<<dim3(ADIM / 32, B * TIN / 32), 256>>>(memory, memW, pmem, ADIM, E, 0);
    pack_weights<<<2048, 256>>>(aWih, aWhh, abih, abhh, dWih, dWhh, dbih, dbhh,
                                qW, projW, gateW);

    // ---- whole 400-step recurrence: one persistent kernel ----
    decoder_loop<<<NBLK, 256>>>(memory, mlen, convW, convb, locW, vW,
                                projb, gateb, out);
}